// round 1
// baseline (speedup 1.0000x reference)
#include <cuda_runtime.h>
#include <math.h>

#define EPS_BN 1e-5f

// ---- problem constants (shapes fixed by the dataset) ----
#define B_EP   32
#define NS     200
#define NQ     100
#define NWAY   20
#define CIN    8
#define LIN    512
#define FDIM   128
#define NSUP   (B_EP*NS)     // 6400
#define NQRY   (B_EP*NQ)     // 3200
#define NTOT   (NSUP+NQRY)   // 9600

// scratch (no allocs allowed -> __device__ globals)
__device__ float g_feat[NTOT*FDIM];            // encoder outputs, support rows 0..6399, query 6400..9599
__device__ float g_proto[B_EP*NWAY*FDIM];

// ---- shared memory layout (float offsets), region R = union(x0+s1, w3) ----
#define OFF_X0   0            // 8 x 516   = 4128
#define OFF_S1   4128         // 32 x 260  = 8320   (R = [0,24576) also holds w3 later)
#define OFF_W3   0            // 128*64*3  = 24576
#define OFF_S2   24576        // 64 x 132  = 8448
#define OFF_W2   33024        // 64*32*3   = 6144
#define OFF_W1   39168        // 32*8*3    = 768
#define OFF_SC1  39936
#define OFF_BI1  39968
#define OFF_SC2  40000
#define OFF_BI2  40064
#define OFF_SC3  40128
#define OFF_BI3  40256
#define OFF_SCF  40384
#define OFF_BIF  40512
#define OFF_F3   40640        // 128
#define OFF_RED  40768        // 32
#define SMEM_FLOATS 40800
#define SMEM_BYTES  (SMEM_FLOATS*4)

// Fused conv1d(k=3,pad=1) + BN + ReLU + maxpool(2) stage.
// Register tile: 4 output channels x 4 conv positions (= 2 pooled positions) per thread.
// Input X is padded: smem idx j holds x[j-1]; idx 0 and idx Lc+1 are zero.
// If MEAN: accumulate mean over pooled positions into f3[o] (requires Q==32:
// one warp covers all pooled positions of its 4 channels -> warp shuffle reduce).
template<int IC, int OC, int Q, int XRS, bool MEAN>
__device__ __forceinline__ void conv_stage(const float* __restrict__ X,
                                           const float* __restrict__ W,
                                           const float* __restrict__ sc,
                                           const float* __restrict__ bi,
                                           float* __restrict__ Y, int YRS,
                                           float* __restrict__ f3, int t)
{
    constexpr int NIT = (OC/4)*Q/256;
    #pragma unroll
    for (int it = 0; it < NIT; ++it) {
        int T  = it*256 + t;
        int q  = T % Q;          // lanes within a warp get consecutive q -> conflict-free float4
        int ot = T / Q;          // uniform within a warp
        int l0 = 4*q, o0 = 4*ot;
        float acc[4][4];
        #pragma unroll
        for (int a = 0; a < 4; ++a)
            #pragma unroll
            for (int b = 0; b < 4; ++b) acc[a][b] = 0.f;

        const float* xcol = X + l0;
        #pragma unroll 4
        for (int i = 0; i < IC; ++i) {
            const float* xr = xcol + i*XRS;
            float4 xa = *reinterpret_cast<const float4*>(xr);      // idx l0..l0+3
            float2 xb = *reinterpret_cast<const float2*>(xr + 4);  // idx l0+4,l0+5
            float x0v=xa.x, x1v=xa.y, x2v=xa.z, x3v=xa.w, x4v=xb.x, x5v=xb.y;
            #pragma unroll
            for (int oo = 0; oo < 4; ++oo) {
                const float* wr = W + (o0+oo)*(IC*3) + i*3;        // broadcast loads
                float w0=wr[0], w1=wr[1], w2=wr[2];
                acc[oo][0] = fmaf(w2,x2v, fmaf(w1,x1v, fmaf(w0,x0v, acc[oo][0])));
                acc[oo][1] = fmaf(w2,x3v, fmaf(w1,x2v, fmaf(w0,x1v, acc[oo][1])));
                acc[oo][2] = fmaf(w2,x4v, fmaf(w1,x3v, fmaf(w0,x2v, acc[oo][2])));
                acc[oo][3] = fmaf(w2,x5v, fmaf(w1,x4v, fmaf(w0,x3v, acc[oo][3])));
            }
        }
        #pragma unroll
        for (int oo = 0; oo < 4; ++oo) {
            int o = o0+oo;
            float s = sc[o], c = bi[o];
            float y0 = fmaxf(fmaf(acc[oo][0], s, c), 0.f);
            float y1 = fmaxf(fmaf(acc[oo][1], s, c), 0.f);
            float y2 = fmaxf(fmaf(acc[oo][2], s, c), 0.f);
            float y3 = fmaxf(fmaf(acc[oo][3], s, c), 0.f);
            float p0 = fmaxf(y0, y1), p1 = fmaxf(y2, y3);
            if constexpr (!MEAN) {
                float* yr = Y + o*YRS + 1 + 2*q;
                yr[0] = p0; yr[1] = p1;
            } else {
                float v = p0 + p1;      // sum of this thread's 2 pooled positions
                #pragma unroll
                for (int sh = 16; sh; sh >>= 1)
                    v += __shfl_xor_sync(0xffffffffu, v, sh);
                if ((t & 31) == 0) f3[o] = v;   // exactly one warp owns each o
            }
        }
    }
}

__global__ __launch_bounds__(256, 1)
void encoder_kernel(const float* __restrict__ s_img, const float* __restrict__ q_img,
                    const float* __restrict__ w1, const float* __restrict__ b1,
                    const float* __restrict__ g1, const float* __restrict__ be1,
                    const float* __restrict__ m1, const float* __restrict__ v1,
                    const float* __restrict__ w2, const float* __restrict__ b2,
                    const float* __restrict__ g2, const float* __restrict__ be2,
                    const float* __restrict__ m2, const float* __restrict__ v2,
                    const float* __restrict__ w3, const float* __restrict__ b3,
                    const float* __restrict__ g3, const float* __restrict__ be3,
                    const float* __restrict__ m3, const float* __restrict__ v3,
                    const float* __restrict__ wf, const float* __restrict__ bf,
                    const float* __restrict__ gf, const float* __restrict__ bef,
                    const float* __restrict__ mf, const float* __restrict__ vf)
{
    extern __shared__ float sm[];
    const int n = blockIdx.x;
    const int t = threadIdx.x;

    float* x0  = sm + OFF_X0;
    float* s1  = sm + OFF_S1;
    float* s2  = sm + OFF_S2;
    float* w1s = sm + OFF_W1;
    float* w2s = sm + OFF_W2;
    float* w3s = sm + OFF_W3;
    float* sc1 = sm + OFF_SC1; float* bi1 = sm + OFF_BI1;
    float* sc2 = sm + OFF_SC2; float* bi2 = sm + OFF_BI2;
    float* sc3 = sm + OFF_SC3; float* bi3 = sm + OFF_BI3;
    float* scf = sm + OFF_SCF; float* bif = sm + OFF_BIF;
    float* f3  = sm + OFF_F3;
    float* red = sm + OFF_RED;

    // ---- phase A: stage input, small weights, folded BN scale/bias, pads ----
    const float* inp = (n < NSUP) ? (s_img + (size_t)n*(CIN*LIN))
                                  : (q_img + (size_t)(n - NSUP)*(CIN*LIN));
    const float4* in4 = reinterpret_cast<const float4*>(inp);
    for (int e = t; e < (CIN*LIN)/4; e += 256) {
        float4 v = __ldg(in4 + e);
        int c = e >> 7;              // 128 float4 per channel
        int l = (e & 127) << 2;
        float* xr = x0 + c*516 + 1 + l;
        xr[0]=v.x; xr[1]=v.y; xr[2]=v.z; xr[3]=v.w;
    }
    if (t < 8)  { x0[t*516]=0.f; x0[t*516+513]=0.f; x0[t*516+514]=0.f; x0[t*516+515]=0.f; }
    if (t < 32) { s1[t*260]=0.f; s1[t*260+257]=0.f; s1[t*260+258]=0.f; s1[t*260+259]=0.f; }
    if (t < 64) { s2[t*132]=0.f; s2[t*132+129]=0.f; s2[t*132+130]=0.f; s2[t*132+131]=0.f; }

    {   // w1: 768 floats, w2: 6144 floats (both contiguous [O][I][3])
        const float4* wg = reinterpret_cast<const float4*>(w1);
        for (int e = t; e < 192; e += 256) reinterpret_cast<float4*>(w1s)[e] = __ldg(wg + e);
        const float4* wg2 = reinterpret_cast<const float4*>(w2);
        for (int e = t; e < 1536; e += 256) reinterpret_cast<float4*>(w2s)[e] = __ldg(wg2 + e);
    }
    if (t < 32)  { float s = g1[t]*rsqrtf(v1[t]+EPS_BN); sc1[t]=s; bi1[t]=(b1[t]-m1[t])*s+be1[t]; }
    if (t < 64)  { float s = g2[t]*rsqrtf(v2[t]+EPS_BN); sc2[t]=s; bi2[t]=(b2[t]-m2[t])*s+be2[t]; }
    if (t < 128) {
        float s3 = g3[t]*rsqrtf(v3[t]+EPS_BN); sc3[t]=s3; bi3[t]=(b3[t]-m3[t])*s3+be3[t];
        float sF = gf[t]*rsqrtf(vf[t]+EPS_BN); scf[t]=sF; bif[t]=(bf[t]-mf[t])*sF+bef[t];
    }
    __syncthreads();

    // ---- stage 1: conv(8->32,L512) + BN + ReLU + pool -> s1[32][256] ----
    conv_stage<8, 32, 128, 516, false>(x0, w1s, sc1, bi1, s1, 260, nullptr, t);
    __syncthreads();

    // ---- stage 2: conv(32->64,L256) -> s2[64][128] ----
    conv_stage<32, 64, 64, 260, false>(s1, w2s, sc2, bi2, s2, 132, nullptr, t);
    __syncthreads();

    // ---- phase B: stage w3 into region R (x0/s1 are dead now) ----
    {
        const float4* wg3 = reinterpret_cast<const float4*>(w3);
        for (int e = t; e < 6144; e += 256) reinterpret_cast<float4*>(w3s)[e] = __ldg(wg3 + e);
    }
    __syncthreads();

    // ---- stage 3: conv(64->128,L128) + pool + sum over 64 pooled -> f3[128] ----
    conv_stage<64, 128, 32, 132, true>(s2, w3s, sc3, bi3, nullptr, 0, f3, t);
    __syncthreads();

    // ---- stage 4: mean, FC, BN, ReLU, L2 normalize ----
    if (t < 128) f3[t] *= (1.0f/64.0f);
    __syncthreads();

    float h = 0.f;
    if (t < 128) {
        const float4* wrow = reinterpret_cast<const float4*>(wf + (size_t)t*FDIM);
        float z = 0.f;
        #pragma unroll
        for (int e = 0; e < 32; ++e) {
            float4 wv = __ldg(wrow + e);
            float4 fv = *reinterpret_cast<const float4*>(f3 + 4*e);
            z = fmaf(wv.x, fv.x, z); z = fmaf(wv.y, fv.y, z);
            z = fmaf(wv.z, fv.z, z); z = fmaf(wv.w, fv.w, z);
        }
        h = fmaxf(fmaf(z, scf[t], bif[t]), 0.f);
        float r2 = h*h;
        #pragma unroll
        for (int sh = 16; sh; sh >>= 1) r2 += __shfl_xor_sync(0xffffffffu, r2, sh);
        if ((t & 31) == 0) red[t >> 5] = r2;
    }
    __syncthreads();
    if (t == 0) {
        float s = red[0] + red[1] + red[2] + red[3];
        red[8] = 1.0f / fmaxf(sqrtf(s), 1e-12f);
    }
    __syncthreads();
    if (t < 128) g_feat[(size_t)n*FDIM + t] = h * red[8];
}

// ---- prototypes: segment-mean of support features per episode ----
__global__ __launch_bounds__(256)
void proto_kernel(const int* __restrict__ s_lab)
{
    __shared__ float proto[NWAY*FDIM];
    __shared__ float cnt[NWAY];
    const int b = blockIdx.x, t = threadIdx.x;
    for (int e = t; e < NWAY*FDIM; e += 256) proto[e] = 0.f;
    if (t < NWAY) cnt[t] = 0.f;
    __syncthreads();

    const int g = t >> 7, f = t & 127;
    for (int s = g; s < NS; s += 2) {
        int lab = __ldg(s_lab + b*NS + s);
        atomicAdd(&proto[lab*FDIM + f], g_feat[(size_t)(b*NS + s)*FDIM + f]);
    }
    for (int s = t; s < NS; s += 256) atomicAdd(&cnt[__ldg(s_lab + b*NS + s)], 1.f);
    __syncthreads();

    for (int e = t; e < NWAY*FDIM; e += 256)
        g_proto[(size_t)b*NWAY*FDIM + e] = proto[e] / cnt[e >> 7];
}

// ---- distances: out[b,q,w] = -sqrt(sum_f (qf-proto)^2) ----
__global__ __launch_bounds__(256)
void dist_kernel(float* __restrict__ out)
{
    __shared__ float proto[NWAY*132];   // padded stride to stagger banks
    const int b = blockIdx.x, t = threadIdx.x;
    for (int e = t; e < NWAY*FDIM; e += 256)
        proto[(e >> 7)*132 + (e & 127)] = g_proto[(size_t)b*NWAY*FDIM + e];
    __syncthreads();

    for (int pr = t; pr < NQ*NWAY; pr += 256) {
        int q = pr / NWAY, w = pr % NWAY;
        const float4* qf = reinterpret_cast<const float4*>(
            g_feat + (size_t)(NSUP + b*NQ + q)*FDIM);
        const float4* pw = reinterpret_cast<const float4*>(proto + w*132);
        float d = 0.f;
        #pragma unroll
        for (int e = 0; e < 32; ++e) {
            float4 a = __ldg(qf + e);
            float4 p = pw[e];
            float dx = a.x-p.x, dy = a.y-p.y, dz = a.z-p.z, dw = a.w-p.w;
            d = fmaf(dx,dx, fmaf(dy,dy, fmaf(dz,dz, fmaf(dw,dw, d))));
        }
        out[(size_t)b*NQ*NWAY + pr] = -sqrtf(fmaxf(d, 0.f));
    }
}

extern "C" void kernel_launch(void* const* d_in, const int* in_sizes, int n_in,
                              void* d_out, int out_size)
{
    const float* s_img = (const float*)d_in[0];
    const float* q_img = (const float*)d_in[1];
    const int*   s_lab = (const int*)  d_in[2];
    const float* w1  = (const float*)d_in[3];
    const float* b1  = (const float*)d_in[4];
    const float* g1  = (const float*)d_in[5];
    const float* be1 = (const float*)d_in[6];
    const float* m1  = (const float*)d_in[7];
    const float* v1  = (const float*)d_in[8];
    const float* w2  = (const float*)d_in[9];
    const float* b2  = (const float*)d_in[10];
    const float* g2  = (const float*)d_in[11];
    const float* be2 = (const float*)d_in[12];
    const float* m2  = (const float*)d_in[13];
    const float* v2  = (const float*)d_in[14];
    const float* w3  = (const float*)d_in[15];
    const float* b3  = (const float*)d_in[16];
    const float* g3  = (const float*)d_in[17];
    const float* be3 = (const float*)d_in[18];
    const float* m3  = (const float*)d_in[19];
    const float* v3  = (const float*)d_in[20];
    const float* wf  = (const float*)d_in[21];
    const float* bf  = (const float*)d_in[22];
    const float* gf  = (const float*)d_in[23];
    const float* bef = (const float*)d_in[24];
    const float* mf  = (const float*)d_in[25];
    const float* vf  = (const float*)d_in[26];
    float* out = (float*)d_out;

    cudaFuncSetAttribute(encoder_kernel,
                         cudaFuncAttributeMaxDynamicSharedMemorySize, SMEM_BYTES);

    encoder_kernel<<<NTOT, 256, SMEM_BYTES>>>(
        s_img, q_img,
        w1, b1, g1, be1, m1, v1,
        w2, b2, g2, be2, m2, v2,
        w3, b3, g3, be3, m3, v3,
        wf, bf, gf, bef, mf, vf);
    proto_kernel<<<B_EP, 256>>>(s_lab);
    dist_kernel<<<B_EP, 256>>>(out);
}

// round 2
// speedup vs baseline: 1.0754x; 1.0754x over previous
#include <cuda_runtime.h>
#include <math.h>

#define EPS_BN 1e-5f

// ---- problem constants ----
#define B_EP   32
#define NS     200
#define NQ     100
#define NWAY   20
#define CIN    8
#define LIN    512
#define FDIM   128
#define NSUP   (B_EP*NS)     // 6400
#define NQRY   (B_EP*NQ)     // 3200
#define NTOT   (NSUP+NQRY)   // 9600
#define NT     512           // threads per encoder CTA

typedef unsigned long long ull;

// scratch (no allocs allowed -> __device__ globals)
__device__ float g_feat[NTOT*FDIM];
__device__ float g_proto[B_EP*NWAY*FDIM];

// ---- shared memory layout (float offsets) ----
#define OFF_X0   0            // 8 x 516   = 4128
#define OFF_S1   4128         // 32 x 260  = 8320   (region reused by w3)
#define OFF_W3   0            // 128*64*3  = 24576 floats (as 12288 float2 pairs)
#define OFF_S2   24576        // 64 x 132  = 8448
#define OFF_W2   33024        // 64*32*3   = 6144
#define OFF_W1   39168        // 32*8*3    = 768
#define OFF_SC1  39936
#define OFF_BI1  39968
#define OFF_SC2  40000
#define OFF_BI2  40064
#define OFF_SC3  40128
#define OFF_BI3  40256
#define OFF_SCF  40384
#define OFF_BIF  40512
#define OFF_F3   40640
#define OFF_RED  40768
#define SMEM_FLOATS 40800
#define SMEM_BYTES  (SMEM_FLOATS*4)

// ---- packed f32x2 helpers (sm_103a FFMA2 path) ----
__device__ __forceinline__ ull ffma2(ull a, ull b, ull c) {
    ull d;
    asm("fma.rn.f32x2 %0, %1, %2, %3;" : "=l"(d) : "l"(a), "l"(b), "l"(c));
    return d;
}
__device__ __forceinline__ ull splat2(float x) {
    ull d;
    asm("mov.b64 %0, {%1, %1};" : "=l"(d) : "f"(x));
    return d;
}
__device__ __forceinline__ void unpack2(ull v, float& lo, float& hi) {
    asm("mov.b64 {%0, %1}, %2;" : "=f"(lo), "=f"(hi) : "l"(v));
}

// Stage conv weights W[OC][IC][3] (global) into smem as channel-PAIR interleaved
// float2 rows: Wp[o/2][r] = (W[2*(o/2)][r], W[2*(o/2)+1][r]), r in [0, IC*3).
template<int IC3, int TOT>
__device__ __forceinline__ void stage_w_pairs(const float* __restrict__ W,
                                              float* __restrict__ Wp, int t)
{
    for (int f = t; f < TOT; f += NT) {
        int o = f / IC3, r = f - o*IC3;
        Wp[(o >> 1)*(2*IC3) + 2*r + (o & 1)] = __ldg(W + f);
    }
}

// Fused conv1d(k=3,pad=1) + BN + ReLU + maxpool(2) with packed f32x2 math.
// Register tile: 4 output channels (2 packed pairs) x 4 conv positions per thread.
template<int IC, int OC, int Q, int XRS, bool MEAN>
__device__ __forceinline__ void conv_stage(const float* __restrict__ X,
                                           const ull* __restrict__ Wp,
                                           const float* __restrict__ sc,
                                           const float* __restrict__ bi,
                                           float* __restrict__ Y, int YRS,
                                           float* __restrict__ f3, int t)
{
    constexpr int IC3 = IC*3;
    constexpr int NIT = (OC/4)*Q/NT;
    #pragma unroll
    for (int it = 0; it < NIT; ++it) {
        int T  = it*NT + t;
        int q  = T % Q;          // consecutive within a warp -> conflict-free float4
        int ot = T / Q;          // uniform within a warp
        int l0 = 4*q, o0 = 4*ot;
        ull acc[2][4];
        #pragma unroll
        for (int p = 0; p < 2; ++p)
            #pragma unroll
            for (int b = 0; b < 4; ++b) acc[p][b] = 0ull;

        const ull* w0r = Wp + (o0 >> 1)*IC3;   // pair (o0, o0+1)
        const ull* w1r = w0r + IC3;            // pair (o0+2, o0+3)
        const float* xcol = X + l0;
        #pragma unroll 4
        for (int i = 0; i < IC; ++i) {
            const float* xr = xcol + i*XRS;
            float4 xa = *reinterpret_cast<const float4*>(xr);
            float2 xb = *reinterpret_cast<const float2*>(xr + 4);
            ull xs0 = splat2(xa.x), xs1 = splat2(xa.y), xs2 = splat2(xa.z);
            ull xs3 = splat2(xa.w), xs4 = splat2(xb.x), xs5 = splat2(xb.y);
            ull wa0 = w0r[3*i], wa1 = w0r[3*i+1], wa2 = w0r[3*i+2];
            ull wb0 = w1r[3*i], wb1 = w1r[3*i+1], wb2 = w1r[3*i+2];
            acc[0][0] = ffma2(wa2, xs2, ffma2(wa1, xs1, ffma2(wa0, xs0, acc[0][0])));
            acc[0][1] = ffma2(wa2, xs3, ffma2(wa1, xs2, ffma2(wa0, xs1, acc[0][1])));
            acc[0][2] = ffma2(wa2, xs4, ffma2(wa1, xs3, ffma2(wa0, xs2, acc[0][2])));
            acc[0][3] = ffma2(wa2, xs5, ffma2(wa1, xs4, ffma2(wa0, xs3, acc[0][3])));
            acc[1][0] = ffma2(wb2, xs2, ffma2(wb1, xs1, ffma2(wb0, xs0, acc[1][0])));
            acc[1][1] = ffma2(wb2, xs3, ffma2(wb1, xs2, ffma2(wb0, xs1, acc[1][1])));
            acc[1][2] = ffma2(wb2, xs4, ffma2(wb1, xs3, ffma2(wb0, xs2, acc[1][2])));
            acc[1][3] = ffma2(wb2, xs5, ffma2(wb1, xs4, ffma2(wb0, xs3, acc[1][3])));
        }
        #pragma unroll
        for (int p = 0; p < 2; ++p) {
            int cA = o0 + 2*p, cB = cA + 1;
            float sA = sc[cA], bA = bi[cA], sB = sc[cB], bB = bi[cB];
            float a0,b0,a1,b1,a2,b2,a3,b3;
            unpack2(acc[p][0], a0, b0); unpack2(acc[p][1], a1, b1);
            unpack2(acc[p][2], a2, b2); unpack2(acc[p][3], a3, b3);
            float yA0 = fmaxf(fmaf(a0, sA, bA), 0.f), yA1 = fmaxf(fmaf(a1, sA, bA), 0.f);
            float yA2 = fmaxf(fmaf(a2, sA, bA), 0.f), yA3 = fmaxf(fmaf(a3, sA, bA), 0.f);
            float yB0 = fmaxf(fmaf(b0, sB, bB), 0.f), yB1 = fmaxf(fmaf(b1, sB, bB), 0.f);
            float yB2 = fmaxf(fmaf(b2, sB, bB), 0.f), yB3 = fmaxf(fmaf(b3, sB, bB), 0.f);
            float pA0 = fmaxf(yA0, yA1), pA1 = fmaxf(yA2, yA3);
            float pB0 = fmaxf(yB0, yB1), pB1 = fmaxf(yB2, yB3);
            if constexpr (!MEAN) {
                float* yrA = Y + cA*YRS + 1 + 2*q;
                float* yrB = Y + cB*YRS + 1 + 2*q;
                yrA[0] = pA0; yrA[1] = pA1;
                yrB[0] = pB0; yrB[1] = pB1;
            } else {
                float vA = pA0 + pA1;
                float vB = pB0 + pB1;
                #pragma unroll
                for (int sh = 16; sh; sh >>= 1) {
                    vA += __shfl_xor_sync(0xffffffffu, vA, sh);
                    vB += __shfl_xor_sync(0xffffffffu, vB, sh);
                }
                if ((t & 31) == 0) { f3[cA] = vA; f3[cB] = vB; }
            }
        }
    }
}

__global__ __launch_bounds__(NT, 1)
void encoder_kernel(const float* __restrict__ s_img, const float* __restrict__ q_img,
                    const float* __restrict__ w1, const float* __restrict__ b1,
                    const float* __restrict__ g1, const float* __restrict__ be1,
                    const float* __restrict__ m1, const float* __restrict__ v1,
                    const float* __restrict__ w2, const float* __restrict__ b2,
                    const float* __restrict__ g2, const float* __restrict__ be2,
                    const float* __restrict__ m2, const float* __restrict__ v2,
                    const float* __restrict__ w3, const float* __restrict__ b3,
                    const float* __restrict__ g3, const float* __restrict__ be3,
                    const float* __restrict__ m3, const float* __restrict__ v3,
                    const float* __restrict__ wf, const float* __restrict__ bf,
                    const float* __restrict__ gf, const float* __restrict__ bef,
                    const float* __restrict__ mf, const float* __restrict__ vf)
{
    extern __shared__ float sm[];
    const int n = blockIdx.x;
    const int t = threadIdx.x;

    float* x0  = sm + OFF_X0;
    float* s1  = sm + OFF_S1;
    float* s2  = sm + OFF_S2;
    float* w1s = sm + OFF_W1;
    float* w2s = sm + OFF_W2;
    float* w3s = sm + OFF_W3;
    float* sc1 = sm + OFF_SC1; float* bi1 = sm + OFF_BI1;
    float* sc2 = sm + OFF_SC2; float* bi2 = sm + OFF_BI2;
    float* sc3 = sm + OFF_SC3; float* bi3 = sm + OFF_BI3;
    float* scf = sm + OFF_SCF; float* bif = sm + OFF_BIF;
    float* f3  = sm + OFF_F3;
    float* red = sm + OFF_RED;

    // ---- phase A: stage input, small weights (pair-interleaved), BN fold, pads ----
    const float* inp = (n < NSUP) ? (s_img + (size_t)n*(CIN*LIN))
                                  : (q_img + (size_t)(n - NSUP)*(CIN*LIN));
    const float4* in4 = reinterpret_cast<const float4*>(inp);
    for (int e = t; e < (CIN*LIN)/4; e += NT) {
        float4 v = __ldg(in4 + e);
        int c = e >> 7;
        int l = (e & 127) << 2;
        float* xr = x0 + c*516 + 1 + l;
        xr[0]=v.x; xr[1]=v.y; xr[2]=v.z; xr[3]=v.w;
    }
    if (t < 8)  { x0[t*516]=0.f; x0[t*516+513]=0.f; x0[t*516+514]=0.f; x0[t*516+515]=0.f; }
    if (t < 32) { s1[t*260]=0.f; s1[t*260+257]=0.f; s1[t*260+258]=0.f; s1[t*260+259]=0.f; }
    if (t < 64) { s2[t*132]=0.f; s2[t*132+129]=0.f; s2[t*132+130]=0.f; s2[t*132+131]=0.f; }

    stage_w_pairs<CIN*3, 32*CIN*3>(w1, w1s, t);
    stage_w_pairs<32*3, 64*32*3>(w2, w2s, t);

    if (t < 32)  { float s = g1[t]*rsqrtf(v1[t]+EPS_BN); sc1[t]=s; bi1[t]=(b1[t]-m1[t])*s+be1[t]; }
    if (t < 64)  { float s = g2[t]*rsqrtf(v2[t]+EPS_BN); sc2[t]=s; bi2[t]=(b2[t]-m2[t])*s+be2[t]; }
    if (t < 128) {
        float s3 = g3[t]*rsqrtf(v3[t]+EPS_BN); sc3[t]=s3; bi3[t]=(b3[t]-m3[t])*s3+be3[t];
        float sF = gf[t]*rsqrtf(vf[t]+EPS_BN); scf[t]=sF; bif[t]=(bf[t]-mf[t])*sF+bef[t];
    }
    __syncthreads();

    // ---- stage 1: conv(8->32,L512) -> s1[32][256] ----
    conv_stage<8, 32, 128, 516, false>(x0, reinterpret_cast<const ull*>(w1s),
                                       sc1, bi1, s1, 260, nullptr, t);
    __syncthreads();

    // ---- stage 2: conv(32->64,L256) -> s2[64][128] ----
    conv_stage<32, 64, 64, 260, false>(s1, reinterpret_cast<const ull*>(w2s),
                                       sc2, bi2, s2, 132, nullptr, t);
    __syncthreads();

    // ---- phase B: stage w3 (pair-interleaved) into region R (x0/s1 dead) ----
    stage_w_pairs<64*3, 128*64*3>(w3, w3s, t);
    __syncthreads();

    // ---- stage 3: conv(64->128,L128) + pool + sum -> f3[128] ----
    conv_stage<64, 128, 32, 132, true>(s2, reinterpret_cast<const ull*>(w3s),
                                       sc3, bi3, nullptr, 0, f3, t);
    __syncthreads();

    // ---- stage 4: mean, FC, BN, ReLU, L2 normalize ----
    if (t < 128) f3[t] *= (1.0f/64.0f);
    __syncthreads();

    float h = 0.f;
    if (t < 128) {
        const float4* wrow = reinterpret_cast<const float4*>(wf + (size_t)t*FDIM);
        float z = 0.f;
        #pragma unroll
        for (int e = 0; e < 32; ++e) {
            float4 wv = __ldg(wrow + e);
            float4 fv = *reinterpret_cast<const float4*>(f3 + 4*e);
            z = fmaf(wv.x, fv.x, z); z = fmaf(wv.y, fv.y, z);
            z = fmaf(wv.z, fv.z, z); z = fmaf(wv.w, fv.w, z);
        }
        h = fmaxf(fmaf(z, scf[t], bif[t]), 0.f);
        float r2 = h*h;
        #pragma unroll
        for (int sh = 16; sh; sh >>= 1) r2 += __shfl_xor_sync(0xffffffffu, r2, sh);
        if ((t & 31) == 0) red[t >> 5] = r2;
    }
    __syncthreads();
    if (t == 0) {
        float s = red[0] + red[1] + red[2] + red[3];
        red[8] = 1.0f / fmaxf(sqrtf(s), 1e-12f);
    }
    __syncthreads();
    if (t < 128) g_feat[(size_t)n*FDIM + t] = h * red[8];
}

// ---- prototypes: segment-mean of support features per episode ----
__global__ __launch_bounds__(256)
void proto_kernel(const int* __restrict__ s_lab)
{
    __shared__ float proto[NWAY*FDIM];
    __shared__ float cnt[NWAY];
    const int b = blockIdx.x, t = threadIdx.x;
    for (int e = t; e < NWAY*FDIM; e += 256) proto[e] = 0.f;
    if (t < NWAY) cnt[t] = 0.f;
    __syncthreads();

    const int g = t >> 7, f = t & 127;
    for (int s = g; s < NS; s += 2) {
        int lab = __ldg(s_lab + b*NS + s);
        atomicAdd(&proto[lab*FDIM + f], g_feat[(size_t)(b*NS + s)*FDIM + f]);
    }
    for (int s = t; s < NS; s += 256) atomicAdd(&cnt[__ldg(s_lab + b*NS + s)], 1.f);
    __syncthreads();

    for (int e = t; e < NWAY*FDIM; e += 256)
        g_proto[(size_t)b*NWAY*FDIM + e] = proto[e] / cnt[e >> 7];
}

// ---- distances: out[b,q,w] = -sqrt(sum_f (qf-proto)^2) ----
__global__ __launch_bounds__(256)
void dist_kernel(float* __restrict__ out)
{
    __shared__ float proto[NWAY*132];
    const int b = blockIdx.x, t = threadIdx.x;
    for (int e = t; e < NWAY*FDIM; e += 256)
        proto[(e >> 7)*132 + (e & 127)] = g_proto[(size_t)b*NWAY*FDIM + e];
    __syncthreads();

    for (int pr = t; pr < NQ*NWAY; pr += 256) {
        int q = pr / NWAY, w = pr % NWAY;
        const float4* qf = reinterpret_cast<const float4*>(
            g_feat + (size_t)(NSUP + b*NQ + q)*FDIM);
        const float4* pw = reinterpret_cast<const float4*>(proto + w*132);
        float d = 0.f;
        #pragma unroll
        for (int e = 0; e < 32; ++e) {
            float4 a = __ldg(qf + e);
            float4 p = pw[e];
            float dx = a.x-p.x, dy = a.y-p.y, dz = a.z-p.z, dw = a.w-p.w;
            d = fmaf(dx,dx, fmaf(dy,dy, fmaf(dz,dz, fmaf(dw,dw, d))));
        }
        out[(size_t)b*NQ*NWAY + pr] = -sqrtf(fmaxf(d, 0.f));
    }
}

extern "C" void kernel_launch(void* const* d_in, const int* in_sizes, int n_in,
                              void* d_out, int out_size)
{
    const float* s_img = (const float*)d_in[0];
    const float* q_img = (const float*)d_in[1];
    const int*   s_lab = (const int*)  d_in[2];
    const float* w1  = (const float*)d_in[3];
    const float* b1  = (const float*)d_in[4];
    const float* g1  = (const float*)d_in[5];
    const float* be1 = (const float*)d_in[6];
    const float* m1  = (const float*)d_in[7];
    const float* v1  = (const float*)d_in[8];
    const float* w2  = (const float*)d_in[9];
    const float* b2  = (const float*)d_in[10];
    const float* g2  = (const float*)d_in[11];
    const float* be2 = (const float*)d_in[12];
    const float* m2  = (const float*)d_in[13];
    const float* v2  = (const float*)d_in[14];
    const float* w3  = (const float*)d_in[15];
    const float* b3  = (const float*)d_in[16];
    const float* g3  = (const float*)d_in[17];
    const float* be3 = (const float*)d_in[18];
    const float* m3  = (const float*)d_in[19];
    const float* v3  = (const float*)d_in[20];
    const float* wf  = (const float*)d_in[21];
    const float* bf  = (const float*)d_in[22];
    const float* gf  = (const float*)d_in[23];
    const float* bef = (const float*)d_in[24];
    const float* mf  = (const float*)d_in[25];
    const float* vf  = (const float*)d_in[26];
    float* out = (float*)d_out;

    cudaFuncSetAttribute(encoder_kernel,
                         cudaFuncAttributeMaxDynamicSharedMemorySize, SMEM_BYTES);

    encoder_kernel<<<NTOT, NT, SMEM_BYTES>>>(
        s_img, q_img,
        w1, b1, g1, be1, m1, v1,
        w2, b2, g2, be2, m2, v2,
        w3, b3, g3, be3, m3, v3,
        wf, bf, gf, bef, mf, vf);
    proto_kernel<<<B_EP, 256>>>(s_lab);
    dist_kernel<<<B_EP, 256>>>(out);
}